// round 10
// baseline (speedup 1.0000x reference)
#include <cuda_runtime.h>

// CanonConv: out[b,t,c] = x[b,t,c] + bias[c] + sum_{k=0..3} w[c,k] * x[b, t+k-3, c]
// x: (B=4, T=4096, C=2048) fp32, row-major. weight: (C,4). bias: (C,).
//
// R1: S=64: occ 40%, DRAM 57%, 50.8us.
// R2: S=32, unroll 8, __stcs: DRAM 70.8%, occ 40.5% (reg-capped), 40.3us.
// R3: S=16, launch_bounds(128,9): regs 56, occ 49.2%, DRAM 71.8%, 38.2us.
//     Perf tracks resident warps ~linearly; still latency-exposed (issue 15%).
// R8: S=8 + launch_bounds(128,10) (regs<=51, 40 warps/SM), __ldcs streaming
//     reads, fold residual add into fma(xc, w3+1, bias).

#define BB 4
#define TT 4096
#define CC 2048
#define CV (CC / 4)       // 512 float4 channel-vectors per row
#define S  8              // timesteps per block strip
#define TPB 128           // threads per block (covers 128 cvecs)

__global__ __launch_bounds__(TPB, 10) void canonconv_kernel(
    const float* __restrict__ x,
    const float* __restrict__ w,      // (C, 4)
    const float* __restrict__ bias,   // (C,)
    float* __restrict__ out)
{
    const int cvec = blockIdx.y * TPB + threadIdx.x;   // 0..511
    const int c    = cvec * 4;
    const int b    = blockIdx.z;
    const int t0   = blockIdx.x * S;

    const float4* __restrict__ x4 = reinterpret_cast<const float4*>(x);
    float4* __restrict__ o4       = reinterpret_cast<float4*>(out);

    // per-channel weight rows: wr[j] = (w[c+j,0..3]); fold +1 into tap 3 so the
    // residual (out += x[t]) costs nothing: fma(xc, w3+1, bias).
    const float4* __restrict__ w4 = reinterpret_cast<const float4*>(w);
    float4 wr0 = w4[c + 0];
    float4 wr1 = w4[c + 1];
    float4 wr2 = w4[c + 2];
    float4 wr3 = w4[c + 3];
    wr0.w += 1.0f; wr1.w += 1.0f; wr2.w += 1.0f; wr3.w += 1.0f;
    const float4 bi = reinterpret_cast<const float4*>(bias)[cvec];

    // max index 4*4096*512 = 8.4M float4s -> fits int
    int idx = (b * TT + t0) * CV + cvec;

    const float4 zero = make_float4(0.f, 0.f, 0.f, 0.f);
    // sliding window: x at t0-3, t0-2, t0-1 (t0 is a multiple of S)
    float4 xm3 = (t0 >= 3) ? __ldcs(&x4[idx - 3 * CV]) : zero;
    float4 xm2 = (t0 >= 2) ? __ldcs(&x4[idx - 2 * CV]) : zero;
    float4 xm1 = (t0 >= 1) ? __ldcs(&x4[idx - 1 * CV]) : zero;

#pragma unroll
    for (int i = 0; i < S; i++) {
        const float4 xc = __ldcs(&x4[idx]);
        float4 r;
        r.x = fmaf(xm3.x, wr0.x, fmaf(xm2.x, wr0.y, fmaf(xm1.x, wr0.z, fmaf(xc.x, wr0.w, bi.x))));
        r.y = fmaf(xm3.y, wr1.x, fmaf(xm2.y, wr1.y, fmaf(xm1.y, wr1.z, fmaf(xc.y, wr1.w, bi.y))));
        r.z = fmaf(xm3.z, wr2.x, fmaf(xm2.z, wr2.y, fmaf(xm1.z, wr2.z, fmaf(xc.z, wr2.w, bi.z))));
        r.w = fmaf(xm3.w, wr3.x, fmaf(xm2.w, wr3.y, fmaf(xm1.w, wr3.z, fmaf(xc.w, wr3.w, bi.w))));
        __stcs(&o4[idx], r);   // streaming store: don't pollute L2
        xm3 = xm2; xm2 = xm1; xm1 = xc;
        idx += CV;
    }
}

extern "C" void kernel_launch(void* const* d_in, const int* in_sizes, int n_in,
                              void* d_out, int out_size)
{
    const float* x    = (const float*)d_in[0];
    const float* w    = (const float*)d_in[1];
    const float* bias = (const float*)d_in[2];
    float* out        = (float*)d_out;

    dim3 grid(TT / S, CV / TPB, BB);   // (512, 4, 4) = 8192 CTAs
    dim3 block(TPB);
    canonconv_kernel<<<grid, block>>>(x, w, bias, out);
}

// round 11
// speedup vs baseline: 1.0123x; 1.0123x over previous
#include <cuda_runtime.h>

// CanonConv: out[b,t,c] = x[b,t,c] + bias[c] + sum_{k=0..3} w[c,k] * x[b, t+k-3, c]
// x: (B=4, T=4096, C=2048) fp32, row-major. weight: (C,4). bias: (C,).
//
// R1: S=64: occ 40%, DRAM 57%, 50.8us.
// R2: S=32, unroll 8, __stcs: DRAM 70.8%, occ 40.5%, 40.3us.
// R3: S=16, lb(128,9): regs 56, occ 49.2%, DRAM 71.8%, 38.2us.  <- best
// R8: S=8, lb(128,10), __ldcs reads: REGRESSED 43.3us. __ldcs evict-first
//     defeated halo L2 reuse -> +13% DRAM traffic (matches +13% time exactly).
// R10: S=16 + lb(128,10), DEFAULT-cached reads (halo = L2 hit), __stcs stores,
//      fma fold kept.

#define BB 4
#define TT 4096
#define CC 2048
#define CV (CC / 4)       // 512 float4 channel-vectors per row
#define S  16             // timesteps per block strip
#define TPB 128           // threads per block (covers 128 cvecs)

__global__ __launch_bounds__(TPB, 10) void canonconv_kernel(
    const float* __restrict__ x,
    const float* __restrict__ w,      // (C, 4)
    const float* __restrict__ bias,   // (C,)
    float* __restrict__ out)
{
    const int cvec = blockIdx.y * TPB + threadIdx.x;   // 0..511
    const int c    = cvec * 4;
    const int b    = blockIdx.z;
    const int t0   = blockIdx.x * S;

    const float4* __restrict__ x4 = reinterpret_cast<const float4*>(x);
    float4* __restrict__ o4       = reinterpret_cast<float4*>(out);

    // per-channel weight rows: wr[j] = (w[c+j,0..3]); fold +1 into tap 3 so the
    // residual (out += x[t]) is free: fma(xc, w3+1, bias).
    const float4* __restrict__ w4 = reinterpret_cast<const float4*>(w);
    float4 wr0 = w4[c + 0];
    float4 wr1 = w4[c + 1];
    float4 wr2 = w4[c + 2];
    float4 wr3 = w4[c + 3];
    wr0.w += 1.0f; wr1.w += 1.0f; wr2.w += 1.0f; wr3.w += 1.0f;
    const float4 bi = reinterpret_cast<const float4*>(bias)[cvec];

    // max index 4*4096*512 = 8.4M float4s -> fits int
    int idx = (b * TT + t0) * CV + cvec;

    const float4 zero = make_float4(0.f, 0.f, 0.f, 0.f);
    // sliding window: x at t0-3, t0-2, t0-1 (t0 is a multiple of S).
    // Default caching: these are the previous strip's freshest body lines -> L2 hits.
    float4 xm3 = (t0 >= 3) ? x4[idx - 3 * CV] : zero;
    float4 xm2 = (t0 >= 2) ? x4[idx - 2 * CV] : zero;
    float4 xm1 = (t0 >= 1) ? x4[idx - 1 * CV] : zero;

#pragma unroll
    for (int i = 0; i < S; i++) {
        const float4 xc = x4[idx];
        float4 r;
        r.x = fmaf(xm3.x, wr0.x, fmaf(xm2.x, wr0.y, fmaf(xm1.x, wr0.z, fmaf(xc.x, wr0.w, bi.x))));
        r.y = fmaf(xm3.y, wr1.x, fmaf(xm2.y, wr1.y, fmaf(xm1.y, wr1.z, fmaf(xc.y, wr1.w, bi.y))));
        r.z = fmaf(xm3.z, wr2.x, fmaf(xm2.z, wr2.y, fmaf(xm1.z, wr2.z, fmaf(xc.z, wr2.w, bi.z))));
        r.w = fmaf(xm3.w, wr3.x, fmaf(xm2.w, wr3.y, fmaf(xm1.w, wr3.z, fmaf(xc.w, wr3.w, bi.w))));
        __stcs(&o4[idx], r);   // streaming store: output is write-once, keep L2 for halo
        xm3 = xm2; xm2 = xm1; xm1 = xc;
        idx += CV;
    }
}

extern "C" void kernel_launch(void* const* d_in, const int* in_sizes, int n_in,
                              void* d_out, int out_size)
{
    const float* x    = (const float*)d_in[0];
    const float* w    = (const float*)d_in[1];
    const float* bias = (const float*)d_in[2];
    float* out        = (float*)d_out;

    dim3 grid(TT / S, CV / TPB, BB);   // (256, 4, 4) = 4096 CTAs
    dim3 block(TPB);
    canonconv_kernel<<<grid, block>>>(x, w, bias, out);
}